// round 6
// baseline (speedup 1.0000x reference)
#include <cuda_runtime.h>

// MixEHR_Seed: B=64, V=10000, K=64
// out: temp_exp_m_batch [64,64], temp_exp_n [V,K], temp_exp_s [V,K], gamma_sr_sum [K], exp_q_z [1]

#define KD    64
#define BD    64
#define VD    10000
#define TQ    4                 // v per tile
#define NTILE (VD / TQ)         // 2500
#define NBLK  592               // 4 CTAs x 148 SMs
#define ETA_F  0.1f
#define BETA_F 0.05f
#define MU_F   0.05f
#define MINI_F 1e-6f

#define OFF_N   4096
#define OFF_S   644096
#define OFF_GSR 1284096
#define OFF_QZ  1284160

__device__ float g_colS[KD];
__device__ float g_colES[KD];
__device__ float g_colEN[KD];
__device__ float g_scratch[NBLK * BD * KD];   // per-block exp_m partials (9.7 MB)

__device__ __forceinline__ float warp_sum(float x) {
    #pragma unroll
    for (int o = 16; o; o >>= 1)
        x += __shfl_xor_sync(0xffffffffu, x, o);
    return x;
}

__global__ void zero_kernel(float* out) {
    int i = blockIdx.x * blockDim.x + threadIdx.x;
    if (i < BD * KD) out[i] = 0.0f;
    if (i < KD) {
        out[OFF_GSR + i] = 0.0f;
        g_colS[i] = 0.0f; g_colES[i] = 0.0f; g_colEN[i] = 0.0f;
    }
    if (i == 0) out[OFF_QZ] = 0.0f;
}

__global__ void colsum_kernel(const float* __restrict__ seeds,
                              const float* __restrict__ exp_s,
                              const float* __restrict__ exp_n) {
    int tid = blockIdx.x * blockDim.x + threadIdx.x;
    int stride = gridDim.x * blockDim.x;
    float a = 0.0f, b = 0.0f, c = 0.0f;
    for (int i = tid; i < VD * KD; i += stride) {
        a += seeds[i]; b += exp_s[i]; c += exp_n[i];
    }
    int k = tid & (KD - 1);
    atomicAdd(&g_colS[k], a);
    atomicAdd(&g_colES[k], b);
    atomicAdd(&g_colEN[k], c);
}

__global__ __launch_bounds__(256, 4) void main_kernel(
    const float* __restrict__ BOW,
    const float* __restrict__ seeds,
    const float* __restrict__ exp_m,
    const float* __restrict__ exp_s,
    const float* __restrict__ exp_n,
    const float* __restrict__ pi,
    float* __restrict__ out)
{
    __shared__ float2 sh_thlt[BD * KD];     // {theta, log(theta)}  32 KB
    __shared__ float  sh_p[8][TQ * KD];     // partials per warp (N, then S)  8 KB
    __shared__ float  sh_gsr[KD];
    __shared__ float  sh_qz;

    for (int i = threadIdx.x; i < BD * KD; i += blockDim.x) {
        float th = exp_m[i] + ETA_F;
        sh_thlt[i] = make_float2(th, __logf(th));
    }
    if (threadIdx.x < KD) sh_gsr[threadIdx.x] = 0.0f;
    if (threadIdx.x == 0) sh_qz = 0.0f;
    __syncthreads();

    const int lane = threadIdx.x & 31;
    const int warp = threadIdx.x >> 5;
    const int k0 = lane, k1 = lane + 32;
    const int b0 = warp * 8;                // this warp owns b in [b0, b0+8)

    const float invS0 = 1.0f / (MU_F * g_colS[k0] + g_colES[k0]);
    const float invS1 = 1.0f / (MU_F * g_colS[k1] + g_colES[k1]);
    const float invN0 = 1.0f / (BETA_F * (float)VD + g_colEN[k0]);
    const float invN1 = 1.0f / (BETA_F * (float)VD + g_colEN[k1]);
    const float pi0 = pi[k0], pi1 = pi[k1];
    const float q0 = 1.0f - pi0, q1 = 1.0f - pi1;

    float accM0[8], accM1[8];
    #pragma unroll
    for (int j = 0; j < 8; j++) { accM0[j] = 0.0f; accM1[j] = 0.0f; }
    float accGsr0 = 0.0f, accGsr1 = 0.0f, accQz = 0.0f;

    for (int tile = blockIdx.x; tile < NTILE; tile += gridDim.x) {
        const int v0 = tile * TQ;

        // per-row constants
        float crr0[TQ], crr1[TQ], lc0[TQ], lc1[TQ];
        bool rowseed[TQ];
        bool tileseed = false;
        #pragma unroll
        for (int t = 0; t < TQ; t++) {
            const int base = (v0 + t) * KD;
            const float sd0 = seeds[base + k0], sd1 = seeds[base + k1];
            const float pn0 = (BETA_F + exp_n[base + k0]) * invN0;
            const float pn1 = (BETA_F + exp_n[base + k1]) * invN1;
            crr0[t] = (1.0f - sd0) * pn0;
            crr1[t] = (1.0f - sd1) * pn1;
            rowseed[t] = __ballot_sync(0xffffffffu, (sd0 > 0.0f) || (sd1 > 0.0f)) != 0u;
            tileseed |= rowseed[t];
            lc0[t] = __logf(crr0[t] + 1e-30f);
            lc1[t] = __logf(crr1[t] + 1e-30f);
        }

        float aN0[TQ], aN1[TQ], aS0[TQ], aS1[TQ];
        #pragma unroll
        for (int t = 0; t < TQ; t++) { aN0[t]=0.f; aN1[t]=0.f; aS0[t]=0.f; aS1[t]=0.f; }

        if (!tileseed) {
            // ---------------- FAST PATH ----------------
            #pragma unroll
            for (int j = 0; j < 8; j++) {
                const int b = b0 + j;
                const float4 c4 = *reinterpret_cast<const float4*>(BOW + b * VD + v0);
                const float cntv[TQ] = {c4.x, c4.y, c4.z, c4.w};
                const float2 tl0 = sh_thlt[b * KD + k0];
                const float2 tl1 = sh_thlt[b * KD + k1];

                float grr0v[TQ], grr1v[TQ], rpv[TQ];
                #pragma unroll
                for (int t = 0; t < TQ; t++) {
                    grr0v[t] = tl0.x * crr0[t];
                    grr1v[t] = tl1.x * crr1[t];
                    rpv[t] = grr0v[t] + grr1v[t];
                }
                // 4 independent butterflies (ILP covers SHFL latency)
                #pragma unroll
                for (int o = 16; o; o >>= 1) {
                    #pragma unroll
                    for (int t = 0; t < TQ; t++)
                        rpv[t] += __shfl_xor_sync(0xffffffffu, rpv[t], o);
                }
                #pragma unroll
                for (int t = 0; t < TQ; t++) {
                    const float rpm = rpv[t] + MINI_F;
                    const float inv = __fdividef(1.0f, rpm);
                    const float lrp = __logf(rpm);
                    const float g0 = grr0v[t] * inv;
                    const float g1 = grr1v[t] * inv;
                    const float cnt = cntv[t];
                    const float p0 = g0 * cnt, p1 = g1 * cnt;
                    aN0[t] += p0; aN1[t] += p1;
                    accM0[j] += p0; accM1[j] += p1;
                    const float m = (cnt > 0.0f) ? 1.0f : 0.0f;
                    const float e = g0 * ((tl0.y + lc0[t]) - lrp)
                                  + g1 * ((tl1.y + lc1[t]) - lrp);
                    accQz = fmaf(m, e, accQz);
                }
            }
        } else {
            // ---------------- SEED-TILE PATH ----------------
            #pragma unroll
            for (int j = 0; j < 8; j++) {
                const int b = b0 + j;
                const float4 c4 = *reinterpret_cast<const float4*>(BOW + b * VD + v0);
                const float cntv[TQ] = {c4.x, c4.y, c4.z, c4.w};
                const float2 tl0 = sh_thlt[b * KD + k0];
                const float2 tl1 = sh_thlt[b * KD + k1];

                #pragma unroll
                for (int t = 0; t < TQ; t++) {
                    const float cnt = cntv[t];
                    const float m = (cnt > 0.0f) ? 1.0f : 0.0f;
                    if (rowseed[t]) {
                        const int base = (v0 + t) * KD;
                        const float sd0 = seeds[base + k0], sd1 = seeds[base + k1];
                        const float ps0 = (MU_F  + exp_s[base + k0]) * invS0;
                        const float ps1 = (MU_F  + exp_s[base + k1]) * invS1;
                        const float pn0 = (BETA_F + exp_n[base + k0]) * invN0;
                        const float pn1 = (BETA_F + exp_n[base + k1]) * invN1;
                        float gss0 = tl0.x * sd0 * ps0 * pi0;
                        float gss1 = tl1.x * sd1 * ps1 * pi1;
                        float gsr0 = tl0.x * sd0 * pn0 * q0;
                        float gsr1 = tl1.x * sd1 * pn1 * q1;
                        float grr0 = tl0.x * crr0[t];
                        float grr1 = tl1.x * crr1[t];
                        float sp = gss0 + gsr0 + gss1 + gsr1;
                        float rp = grr0 + grr1;
                        #pragma unroll
                        for (int o = 16; o; o >>= 1) {
                            sp += __shfl_xor_sync(0xffffffffu, sp, o);
                            rp += __shfl_xor_sync(0xffffffffu, rp, o);
                        }
                        const float invs = __fdividef(1.0f, sp + MINI_F);
                        const float invr = __fdividef(1.0f, rp + MINI_F);
                        gss0 *= invs; gss1 *= invs;
                        gsr0 *= invs; gsr1 *= invs;
                        grr0 *= invr; grr1 *= invr;
                        const float gam0 = pi0 * gss0 + q0 * (gsr0 + grr0);
                        const float gam1 = pi1 * gss1 + q1 * (gsr1 + grr1);
                        accM0[j] += gam0 * cnt; accM1[j] += gam1 * cnt;
                        aN0[t] += (gsr0 + grr0) * cnt; aN1[t] += (gsr1 + grr1) * cnt;
                        aS0[t] += gss0 * cnt;          aS1[t] += gss1 * cnt;
                        accGsr0 += m * gsr0;           accGsr1 += m * gsr1;
                        accQz += m * (gam0 * __logf(gam0 + MINI_F)
                                    + gam1 * __logf(gam1 + MINI_F));
                    } else {
                        float grr0 = tl0.x * crr0[t];
                        float grr1 = tl1.x * crr1[t];
                        const float rpm = warp_sum(grr0 + grr1) + MINI_F;
                        const float inv = __fdividef(1.0f, rpm);
                        const float lrp = __logf(rpm);
                        const float g0 = grr0 * inv, g1 = grr1 * inv;
                        const float p0 = g0 * cnt, p1 = g1 * cnt;
                        aN0[t] += p0; aN1[t] += p1;
                        accM0[j] += p0; accM1[j] += p1;
                        const float e = g0 * ((tl0.y + lc0[t]) - lrp)
                                      + g1 * ((tl1.y + lc1[t]) - lrp);
                        accQz = fmaf(m, e, accQz);
                    }
                }
            }
        }

        // ---- per-tile cross-warp reduction: N always; S only on seed tiles ----
        #pragma unroll
        for (int t = 0; t < TQ; t++) {
            sh_p[warp][t * KD + k0] = aN0[t];
            sh_p[warp][t * KD + k1] = aN1[t];
        }
        __syncthreads();
        {
            const int tid = threadIdx.x;   // tid = t*64 + k
            float sN = 0.0f;
            #pragma unroll
            for (int w = 0; w < 8; w++) sN += sh_p[w][tid];
            out[OFF_N + v0 * KD + tid] = sN;
            if (!tileseed) out[OFF_S + v0 * KD + tid] = 0.0f;
        }
        if (tileseed) {
            __syncthreads();   // N reads complete before overwrite with S
            #pragma unroll
            for (int t = 0; t < TQ; t++) {
                sh_p[warp][t * KD + k0] = aS0[t];
                sh_p[warp][t * KD + k1] = aS1[t];
            }
            __syncthreads();
            const int tid = threadIdx.x;
            float sS = 0.0f;
            #pragma unroll
            for (int w = 0; w < 8; w++) sS += sh_p[w][tid];
            out[OFF_S + v0 * KD + tid] = sS;
        }
        __syncthreads();       // protect sh_p reuse next tile
    }

    // epilogue: exp_m register partials -> private scratch (no atomics)
    {
        float* dst = g_scratch + blockIdx.x * (BD * KD);
        #pragma unroll
        for (int j = 0; j < 8; j++) {
            dst[(b0 + j) * KD + k0] = accM0[j];
            dst[(b0 + j) * KD + k1] = accM1[j];
        }
    }
    atomicAdd(&sh_gsr[k0], accGsr0);
    atomicAdd(&sh_gsr[k1], accGsr1);
    const float qzw = warp_sum(accQz);
    if (lane == 0) atomicAdd(&sh_qz, qzw);
    __syncthreads();
    if (threadIdx.x < KD) atomicAdd(&out[OFF_GSR + threadIdx.x], sh_gsr[threadIdx.x]);
    if (threadIdx.x == 0) atomicAdd(&out[OFF_QZ], sh_qz);
}

// Sum scratch[NBLK][4096] -> out[0..4095]. float4 lanes; grid (4, 74), 8 slices per y.
__global__ void reduce_m_kernel(float* __restrict__ out) {
    const int i = blockIdx.x * blockDim.x + threadIdx.x;   // 0..1023 (float4 index)
    const int j0 = blockIdx.y * 8;
    const float4* src = reinterpret_cast<const float4*>(g_scratch);
    float4 s = make_float4(0.f, 0.f, 0.f, 0.f);
    #pragma unroll
    for (int j = 0; j < 8; j++) {
        float4 v = src[(j0 + j) * (BD * KD / 4) + i];
        s.x += v.x; s.y += v.y; s.z += v.z; s.w += v.w;
    }
    atomicAdd(&out[i * 4 + 0], s.x);
    atomicAdd(&out[i * 4 + 1], s.y);
    atomicAdd(&out[i * 4 + 2], s.z);
    atomicAdd(&out[i * 4 + 3], s.w);
}

extern "C" void kernel_launch(void* const* d_in, const int* in_sizes, int n_in,
                              void* d_out, int out_size) {
    const float* BOW   = (const float*)d_in[0];
    const float* seeds = (const float*)d_in[1];
    const float* exp_m = (const float*)d_in[2];
    const float* exp_s = (const float*)d_in[3];
    const float* exp_n = (const float*)d_in[4];
    const float* pi    = (const float*)d_in[5];
    float* out = (float*)d_out;

    zero_kernel<<<16, 256>>>(out);
    colsum_kernel<<<148, 256>>>(seeds, exp_s, exp_n);
    main_kernel<<<NBLK, 256>>>(BOW, seeds, exp_m, exp_s, exp_n, pi, out);
    reduce_m_kernel<<<dim3(4, 74), 256>>>(out);
}

// round 7
// speedup vs baseline: 1.0016x; 1.0016x over previous
#include <cuda_runtime.h>

// MixEHR_Seed: B=64, V=10000, K=64
// out: temp_exp_m_batch [64,64], temp_exp_n [V,K], temp_exp_s [V,K], gamma_sr_sum [K], exp_q_z [1]

#define KD    64
#define BD    64
#define VD    10000
#define TQ    4                 // v per tile
#define NTILE (VD / TQ)         // 2500
#define NBLK  592               // 4 CTAs x 148 SMs
#define ETA_F  0.1f
#define BETA_F 0.05f
#define MU_F   0.05f
#define MINI_F 1e-6f

#define OFF_N   4096
#define OFF_S   644096
#define OFF_GSR 1284096
#define OFF_QZ  1284160

__device__ float g_colS[KD];
__device__ float g_colES[KD];
__device__ float g_colEN[KD];
__device__ float g_scratch[NBLK * BD * KD];   // per-block exp_m partials (9.7 MB)

__device__ __forceinline__ float warp_sum(float x) {
    #pragma unroll
    for (int o = 16; o; o >>= 1)
        x += __shfl_xor_sync(0xffffffffu, x, o);
    return x;
}

__global__ void zero_kernel(float* out) {
    int i = blockIdx.x * blockDim.x + threadIdx.x;
    if (i < BD * KD) out[i] = 0.0f;
    if (i < KD) {
        out[OFF_GSR + i] = 0.0f;
        g_colS[i] = 0.0f; g_colES[i] = 0.0f; g_colEN[i] = 0.0f;
    }
    if (i == 0) out[OFF_QZ] = 0.0f;
}

__global__ void colsum_kernel(const float* __restrict__ seeds,
                              const float* __restrict__ exp_s,
                              const float* __restrict__ exp_n) {
    int tid = blockIdx.x * blockDim.x + threadIdx.x;
    int stride = gridDim.x * blockDim.x;
    float a = 0.0f, b = 0.0f, c = 0.0f;
    for (int i = tid; i < VD * KD; i += stride) {
        a += seeds[i]; b += exp_s[i]; c += exp_n[i];
    }
    int k = tid & (KD - 1);
    atomicAdd(&g_colS[k], a);
    atomicAdd(&g_colES[k], b);
    atomicAdd(&g_colEN[k], c);
}

__global__ __launch_bounds__(256, 4) void main_kernel(
    const float* __restrict__ BOW,
    const float* __restrict__ seeds,
    const float* __restrict__ exp_m,
    const float* __restrict__ exp_s,
    const float* __restrict__ exp_n,
    const float* __restrict__ pi,
    float* __restrict__ out)
{
    __shared__ float2 sh_thlt[BD * KD];     // {theta, log(theta)}  32 KB
    __shared__ float  sh_p[8][TQ * KD];     // partials per warp (N, then S)  8 KB
    __shared__ float  sh_gsr[KD];
    __shared__ float  sh_qz;

    for (int i = threadIdx.x; i < BD * KD; i += blockDim.x) {
        float th = exp_m[i] + ETA_F;
        sh_thlt[i] = make_float2(th, __logf(th));
    }
    if (threadIdx.x < KD) sh_gsr[threadIdx.x] = 0.0f;
    if (threadIdx.x == 0) sh_qz = 0.0f;
    __syncthreads();

    const int lane = threadIdx.x & 31;
    const int warp = threadIdx.x >> 5;
    const int k0 = lane, k1 = lane + 32;
    const int b0 = warp * 8;                // this warp owns b in [b0, b0+8)

    const float invS0 = 1.0f / (MU_F * g_colS[k0] + g_colES[k0]);
    const float invS1 = 1.0f / (MU_F * g_colS[k1] + g_colES[k1]);
    const float invN0 = 1.0f / (BETA_F * (float)VD + g_colEN[k0]);
    const float invN1 = 1.0f / (BETA_F * (float)VD + g_colEN[k1]);
    const float pi0 = pi[k0], pi1 = pi[k1];
    const float q0 = 1.0f - pi0, q1 = 1.0f - pi1;

    float accM0[8], accM1[8];
    #pragma unroll
    for (int j = 0; j < 8; j++) { accM0[j] = 0.0f; accM1[j] = 0.0f; }
    float accGsr0 = 0.0f, accGsr1 = 0.0f, accQz = 0.0f;

    for (int tile = blockIdx.x; tile < NTILE; tile += gridDim.x) {
        const int v0 = tile * TQ;

        // per-row constants
        float crr0[TQ], crr1[TQ], lc0[TQ], lc1[TQ];
        bool rowseed[TQ];
        bool tileseed = false;
        #pragma unroll
        for (int t = 0; t < TQ; t++) {
            const int base = (v0 + t) * KD;
            const float sd0 = seeds[base + k0], sd1 = seeds[base + k1];
            const float pn0 = (BETA_F + exp_n[base + k0]) * invN0;
            const float pn1 = (BETA_F + exp_n[base + k1]) * invN1;
            crr0[t] = (1.0f - sd0) * pn0;
            crr1[t] = (1.0f - sd1) * pn1;
            rowseed[t] = __ballot_sync(0xffffffffu, (sd0 > 0.0f) || (sd1 > 0.0f)) != 0u;
            tileseed |= rowseed[t];
            lc0[t] = __logf(crr0[t] + 1e-30f);
            lc1[t] = __logf(crr1[t] + 1e-30f);
        }

        float aN0[TQ], aN1[TQ], aS0[TQ], aS1[TQ];
        #pragma unroll
        for (int t = 0; t < TQ; t++) { aN0[t]=0.f; aN1[t]=0.f; aS0[t]=0.f; aS1[t]=0.f; }

        if (!tileseed) {
            // ---------------- FAST PATH ----------------
            #pragma unroll
            for (int j = 0; j < 8; j++) {
                const int b = b0 + j;
                const float4 c4 = *reinterpret_cast<const float4*>(BOW + b * VD + v0);
                const float cntv[TQ] = {c4.x, c4.y, c4.z, c4.w};
                const float2 tl0 = sh_thlt[b * KD + k0];
                const float2 tl1 = sh_thlt[b * KD + k1];

                float grr0v[TQ], grr1v[TQ], rpv[TQ];
                #pragma unroll
                for (int t = 0; t < TQ; t++) {
                    grr0v[t] = tl0.x * crr0[t];
                    grr1v[t] = tl1.x * crr1[t];
                    rpv[t] = grr0v[t] + grr1v[t];
                }
                // 4 independent butterflies (ILP covers SHFL latency)
                #pragma unroll
                for (int o = 16; o; o >>= 1) {
                    #pragma unroll
                    for (int t = 0; t < TQ; t++)
                        rpv[t] += __shfl_xor_sync(0xffffffffu, rpv[t], o);
                }
                #pragma unroll
                for (int t = 0; t < TQ; t++) {
                    const float rpm = rpv[t] + MINI_F;
                    const float inv = __fdividef(1.0f, rpm);
                    const float lrp = __logf(rpm);
                    const float g0 = grr0v[t] * inv;
                    const float g1 = grr1v[t] * inv;
                    const float cnt = cntv[t];
                    const float p0 = g0 * cnt, p1 = g1 * cnt;
                    aN0[t] += p0; aN1[t] += p1;
                    accM0[j] += p0; accM1[j] += p1;
                    const float m = (cnt > 0.0f) ? 1.0f : 0.0f;
                    const float e = g0 * ((tl0.y + lc0[t]) - lrp)
                                  + g1 * ((tl1.y + lc1[t]) - lrp);
                    accQz = fmaf(m, e, accQz);
                }
            }
        } else {
            // ---------------- SEED-TILE PATH ----------------
            #pragma unroll
            for (int j = 0; j < 8; j++) {
                const int b = b0 + j;
                const float4 c4 = *reinterpret_cast<const float4*>(BOW + b * VD + v0);
                const float cntv[TQ] = {c4.x, c4.y, c4.z, c4.w};
                const float2 tl0 = sh_thlt[b * KD + k0];
                const float2 tl1 = sh_thlt[b * KD + k1];

                #pragma unroll
                for (int t = 0; t < TQ; t++) {
                    const float cnt = cntv[t];
                    const float m = (cnt > 0.0f) ? 1.0f : 0.0f;
                    if (rowseed[t]) {
                        const int base = (v0 + t) * KD;
                        const float sd0 = seeds[base + k0], sd1 = seeds[base + k1];
                        const float ps0 = (MU_F  + exp_s[base + k0]) * invS0;
                        const float ps1 = (MU_F  + exp_s[base + k1]) * invS1;
                        const float pn0 = (BETA_F + exp_n[base + k0]) * invN0;
                        const float pn1 = (BETA_F + exp_n[base + k1]) * invN1;
                        float gss0 = tl0.x * sd0 * ps0 * pi0;
                        float gss1 = tl1.x * sd1 * ps1 * pi1;
                        float gsr0 = tl0.x * sd0 * pn0 * q0;
                        float gsr1 = tl1.x * sd1 * pn1 * q1;
                        float grr0 = tl0.x * crr0[t];
                        float grr1 = tl1.x * crr1[t];
                        float sp = gss0 + gsr0 + gss1 + gsr1;
                        float rp = grr0 + grr1;
                        #pragma unroll
                        for (int o = 16; o; o >>= 1) {
                            sp += __shfl_xor_sync(0xffffffffu, sp, o);
                            rp += __shfl_xor_sync(0xffffffffu, rp, o);
                        }
                        const float invs = __fdividef(1.0f, sp + MINI_F);
                        const float invr = __fdividef(1.0f, rp + MINI_F);
                        gss0 *= invs; gss1 *= invs;
                        gsr0 *= invs; gsr1 *= invs;
                        grr0 *= invr; grr1 *= invr;
                        const float gam0 = pi0 * gss0 + q0 * (gsr0 + grr0);
                        const float gam1 = pi1 * gss1 + q1 * (gsr1 + grr1);
                        accM0[j] += gam0 * cnt; accM1[j] += gam1 * cnt;
                        aN0[t] += (gsr0 + grr0) * cnt; aN1[t] += (gsr1 + grr1) * cnt;
                        aS0[t] += gss0 * cnt;          aS1[t] += gss1 * cnt;
                        accGsr0 += m * gsr0;           accGsr1 += m * gsr1;
                        accQz += m * (gam0 * __logf(gam0 + MINI_F)
                                    + gam1 * __logf(gam1 + MINI_F));
                    } else {
                        float grr0 = tl0.x * crr0[t];
                        float grr1 = tl1.x * crr1[t];
                        const float rpm = warp_sum(grr0 + grr1) + MINI_F;
                        const float inv = __fdividef(1.0f, rpm);
                        const float lrp = __logf(rpm);
                        const float g0 = grr0 * inv, g1 = grr1 * inv;
                        const float p0 = g0 * cnt, p1 = g1 * cnt;
                        aN0[t] += p0; aN1[t] += p1;
                        accM0[j] += p0; accM1[j] += p1;
                        const float e = g0 * ((tl0.y + lc0[t]) - lrp)
                                      + g1 * ((tl1.y + lc1[t]) - lrp);
                        accQz = fmaf(m, e, accQz);
                    }
                }
            }
        }

        // ---- per-tile cross-warp reduction: N always; S only on seed tiles ----
        #pragma unroll
        for (int t = 0; t < TQ; t++) {
            sh_p[warp][t * KD + k0] = aN0[t];
            sh_p[warp][t * KD + k1] = aN1[t];
        }
        __syncthreads();
        {
            const int tid = threadIdx.x;   // tid = t*64 + k
            float sN = 0.0f;
            #pragma unroll
            for (int w = 0; w < 8; w++) sN += sh_p[w][tid];
            out[OFF_N + v0 * KD + tid] = sN;
            if (!tileseed) out[OFF_S + v0 * KD + tid] = 0.0f;
        }
        if (tileseed) {
            __syncthreads();   // N reads complete before overwrite with S
            #pragma unroll
            for (int t = 0; t < TQ; t++) {
                sh_p[warp][t * KD + k0] = aS0[t];
                sh_p[warp][t * KD + k1] = aS1[t];
            }
            __syncthreads();
            const int tid = threadIdx.x;
            float sS = 0.0f;
            #pragma unroll
            for (int w = 0; w < 8; w++) sS += sh_p[w][tid];
            out[OFF_S + v0 * KD + tid] = sS;
        }
        __syncthreads();       // protect sh_p reuse next tile
    }

    // epilogue: exp_m register partials -> private scratch (no atomics)
    {
        float* dst = g_scratch + blockIdx.x * (BD * KD);
        #pragma unroll
        for (int j = 0; j < 8; j++) {
            dst[(b0 + j) * KD + k0] = accM0[j];
            dst[(b0 + j) * KD + k1] = accM1[j];
        }
    }
    atomicAdd(&sh_gsr[k0], accGsr0);
    atomicAdd(&sh_gsr[k1], accGsr1);
    const float qzw = warp_sum(accQz);
    if (lane == 0) atomicAdd(&sh_qz, qzw);
    __syncthreads();
    if (threadIdx.x < KD) atomicAdd(&out[OFF_GSR + threadIdx.x], sh_gsr[threadIdx.x]);
    if (threadIdx.x == 0) atomicAdd(&out[OFF_QZ], sh_qz);
}

// Sum scratch[NBLK][4096] -> out[0..4095]. float4 lanes; grid (4, 74), 8 slices per y.
__global__ void reduce_m_kernel(float* __restrict__ out) {
    const int i = blockIdx.x * blockDim.x + threadIdx.x;   // 0..1023 (float4 index)
    const int j0 = blockIdx.y * 8;
    const float4* src = reinterpret_cast<const float4*>(g_scratch);
    float4 s = make_float4(0.f, 0.f, 0.f, 0.f);
    #pragma unroll
    for (int j = 0; j < 8; j++) {
        float4 v = src[(j0 + j) * (BD * KD / 4) + i];
        s.x += v.x; s.y += v.y; s.z += v.z; s.w += v.w;
    }
    atomicAdd(&out[i * 4 + 0], s.x);
    atomicAdd(&out[i * 4 + 1], s.y);
    atomicAdd(&out[i * 4 + 2], s.z);
    atomicAdd(&out[i * 4 + 3], s.w);
}

extern "C" void kernel_launch(void* const* d_in, const int* in_sizes, int n_in,
                              void* d_out, int out_size) {
    const float* BOW   = (const float*)d_in[0];
    const float* seeds = (const float*)d_in[1];
    const float* exp_m = (const float*)d_in[2];
    const float* exp_s = (const float*)d_in[3];
    const float* exp_n = (const float*)d_in[4];
    const float* pi    = (const float*)d_in[5];
    float* out = (float*)d_out;

    zero_kernel<<<16, 256>>>(out);
    colsum_kernel<<<148, 256>>>(seeds, exp_s, exp_n);
    main_kernel<<<NBLK, 256>>>(BOW, seeds, exp_m, exp_s, exp_n, pi, out);
    reduce_m_kernel<<<dim3(4, 74), 256>>>(out);
}

// round 8
// speedup vs baseline: 1.1122x; 1.1105x over previous
#include <cuda_runtime.h>

// MixEHR_Seed: B=64, V=10000, K=64
// out: temp_exp_m_batch [64,64], temp_exp_n [V,K], temp_exp_s [V,K], gamma_sr_sum [K], exp_q_z [1]

#define KD    64
#define BD    64
#define VD    10000
#define TQ    4                 // v per tile
#define NTILE (VD / TQ)         // 2500
#define NBLK  444               // 3 CTAs x 148 SMs
#define NSLICE 32               // exp_m scratch slices
#define ETA_F  0.1f
#define BETA_F 0.05f
#define MU_F   0.05f
#define MINI_F 1e-6f

#define OFF_N   4096
#define OFF_S   644096
#define OFF_GSR 1284096
#define OFF_QZ  1284160

__device__ float g_colS[KD];
__device__ float g_colES[KD];
__device__ float g_colEN[KD];
__device__ float g_scratch32[NSLICE * BD * KD];   // 512 KB

__device__ __forceinline__ float warp_sum(float x) {
    #pragma unroll
    for (int o = 16; o; o >>= 1)
        x += __shfl_xor_sync(0xffffffffu, x, o);
    return x;
}

__global__ void zero_kernel(float* out) {
    int i = blockIdx.x * blockDim.x + threadIdx.x;     // grid 128*256 = 32768
    if (i < BD * KD) out[i] = 0.0f;
    if (i < KD) {
        out[OFF_GSR + i] = 0.0f;
        g_colS[i] = 0.0f; g_colES[i] = 0.0f; g_colEN[i] = 0.0f;
    }
    if (i == 0) out[OFF_QZ] = 0.0f;
    // scratch32: 131072 floats = 32768 float4
    reinterpret_cast<float4*>(g_scratch32)[i] = make_float4(0.f, 0.f, 0.f, 0.f);
}

__global__ void colsum_kernel(const float* __restrict__ seeds,
                              const float* __restrict__ exp_s,
                              const float* __restrict__ exp_n) {
    int tid = blockIdx.x * blockDim.x + threadIdx.x;
    int stride = gridDim.x * blockDim.x;
    float a = 0.0f, b = 0.0f, c = 0.0f;
    for (int i = tid; i < VD * KD; i += stride) {
        a += seeds[i]; b += exp_s[i]; c += exp_n[i];
    }
    int k = tid & (KD - 1);
    atomicAdd(&g_colS[k], a);
    atomicAdd(&g_colES[k], b);
    atomicAdd(&g_colEN[k], c);
}

__global__ __launch_bounds__(256, 3) void main_kernel(
    const float* __restrict__ BOW,
    const float* __restrict__ seeds,
    const float* __restrict__ exp_m,
    const float* __restrict__ exp_s,
    const float* __restrict__ exp_n,
    const float* __restrict__ pi,
    float* __restrict__ out)
{
    __shared__ float2 sh_thlt[BD * KD];     // {theta, log(theta)}  32 KB
    __shared__ float  sh_pN[8][TQ * KD];    // aN partials per warp  8 KB
    __shared__ float  sh_pS[8][TQ * KD];    // aS partials per warp  8 KB
    __shared__ float  sh_gsr[KD];
    __shared__ float  sh_qz;

    for (int i = threadIdx.x; i < BD * KD; i += blockDim.x) {
        float th = exp_m[i] + ETA_F;
        sh_thlt[i] = make_float2(th, __logf(th));
    }
    if (threadIdx.x < KD) sh_gsr[threadIdx.x] = 0.0f;
    if (threadIdx.x == 0) sh_qz = 0.0f;
    __syncthreads();

    const int lane = threadIdx.x & 31;
    const int warp = threadIdx.x >> 5;
    const int k0 = lane, k1 = lane + 32;
    const int b0 = warp * 8;                // this warp owns b in [b0, b0+8)

    const float invS0 = 1.0f / (MU_F * g_colS[k0] + g_colES[k0]);
    const float invS1 = 1.0f / (MU_F * g_colS[k1] + g_colES[k1]);
    const float invN0 = 1.0f / (BETA_F * (float)VD + g_colEN[k0]);
    const float invN1 = 1.0f / (BETA_F * (float)VD + g_colEN[k1]);
    const float pi0 = pi[k0], pi1 = pi[k1];
    const float q0 = 1.0f - pi0, q1 = 1.0f - pi1;

    float accM0[8], accM1[8];
    #pragma unroll
    for (int j = 0; j < 8; j++) { accM0[j] = 0.0f; accM1[j] = 0.0f; }
    float accGsr0 = 0.0f, accGsr1 = 0.0f, accQz = 0.0f;

    for (int tile = blockIdx.x; tile < NTILE; tile += gridDim.x) {
        const int v0 = tile * TQ;

        // per-row constants
        float crr0[TQ], crr1[TQ], lc0[TQ], lc1[TQ];
        bool rowseed[TQ];
        bool tileseed = false;
        #pragma unroll
        for (int t = 0; t < TQ; t++) {
            const int base = (v0 + t) * KD;
            const float sd0 = seeds[base + k0], sd1 = seeds[base + k1];
            const float pn0 = (BETA_F + exp_n[base + k0]) * invN0;
            const float pn1 = (BETA_F + exp_n[base + k1]) * invN1;
            crr0[t] = (1.0f - sd0) * pn0;
            crr1[t] = (1.0f - sd1) * pn1;
            rowseed[t] = __ballot_sync(0xffffffffu, (sd0 > 0.0f) || (sd1 > 0.0f)) != 0u;
            tileseed |= rowseed[t];
            lc0[t] = __logf(crr0[t] + 1e-30f);
            lc1[t] = __logf(crr1[t] + 1e-30f);
        }

        float aN0[TQ], aN1[TQ], aS0[TQ], aS1[TQ];
        #pragma unroll
        for (int t = 0; t < TQ; t++) { aN0[t]=0.f; aN1[t]=0.f; aS0[t]=0.f; aS1[t]=0.f; }

        if (!tileseed) {
            // ---------------- FAST PATH ----------------
            #pragma unroll
            for (int j = 0; j < 8; j++) {
                const int b = b0 + j;
                const float4 c4 = *reinterpret_cast<const float4*>(BOW + b * VD + v0);
                const float cntv[TQ] = {c4.x, c4.y, c4.z, c4.w};
                const float2 tl0 = sh_thlt[b * KD + k0];
                const float2 tl1 = sh_thlt[b * KD + k1];

                float grr0v[TQ], grr1v[TQ], rpv[TQ];
                #pragma unroll
                for (int t = 0; t < TQ; t++) {
                    grr0v[t] = tl0.x * crr0[t];
                    grr1v[t] = tl1.x * crr1[t];
                    rpv[t] = grr0v[t] + grr1v[t];
                }
                // 4 independent butterflies (ILP covers SHFL latency)
                #pragma unroll
                for (int o = 16; o; o >>= 1) {
                    #pragma unroll
                    for (int t = 0; t < TQ; t++)
                        rpv[t] += __shfl_xor_sync(0xffffffffu, rpv[t], o);
                }
                #pragma unroll
                for (int t = 0; t < TQ; t++) {
                    const float rpm = rpv[t] + MINI_F;
                    const float inv = __fdividef(1.0f, rpm);
                    const float lrp = __logf(rpm);
                    const float g0 = grr0v[t] * inv;
                    const float g1 = grr1v[t] * inv;
                    const float cnt = cntv[t];
                    const float p0 = g0 * cnt, p1 = g1 * cnt;
                    aN0[t] += p0; aN1[t] += p1;
                    accM0[j] += p0; accM1[j] += p1;
                    const float m = (cnt > 0.0f) ? 1.0f : 0.0f;
                    const float e = g0 * ((tl0.y + lc0[t]) - lrp)
                                  + g1 * ((tl1.y + lc1[t]) - lrp);
                    accQz = fmaf(m, e, accQz);
                }
            }
        } else {
            // ---------------- SEED-TILE PATH ----------------
            #pragma unroll
            for (int j = 0; j < 8; j++) {
                const int b = b0 + j;
                const float4 c4 = *reinterpret_cast<const float4*>(BOW + b * VD + v0);
                const float cntv[TQ] = {c4.x, c4.y, c4.z, c4.w};
                const float2 tl0 = sh_thlt[b * KD + k0];
                const float2 tl1 = sh_thlt[b * KD + k1];

                #pragma unroll
                for (int t = 0; t < TQ; t++) {
                    const float cnt = cntv[t];
                    const float m = (cnt > 0.0f) ? 1.0f : 0.0f;
                    if (rowseed[t]) {
                        const int base = (v0 + t) * KD;
                        const float sd0 = seeds[base + k0], sd1 = seeds[base + k1];
                        const float ps0 = (MU_F  + exp_s[base + k0]) * invS0;
                        const float ps1 = (MU_F  + exp_s[base + k1]) * invS1;
                        const float pn0 = (BETA_F + exp_n[base + k0]) * invN0;
                        const float pn1 = (BETA_F + exp_n[base + k1]) * invN1;
                        float gss0 = tl0.x * sd0 * ps0 * pi0;
                        float gss1 = tl1.x * sd1 * ps1 * pi1;
                        float gsr0 = tl0.x * sd0 * pn0 * q0;
                        float gsr1 = tl1.x * sd1 * pn1 * q1;
                        float grr0 = tl0.x * crr0[t];
                        float grr1 = tl1.x * crr1[t];
                        float sp = gss0 + gsr0 + gss1 + gsr1;
                        float rp = grr0 + grr1;
                        #pragma unroll
                        for (int o = 16; o; o >>= 1) {
                            sp += __shfl_xor_sync(0xffffffffu, sp, o);
                            rp += __shfl_xor_sync(0xffffffffu, rp, o);
                        }
                        const float invs = __fdividef(1.0f, sp + MINI_F);
                        const float invr = __fdividef(1.0f, rp + MINI_F);
                        gss0 *= invs; gss1 *= invs;
                        gsr0 *= invs; gsr1 *= invs;
                        grr0 *= invr; grr1 *= invr;
                        const float gam0 = pi0 * gss0 + q0 * (gsr0 + grr0);
                        const float gam1 = pi1 * gss1 + q1 * (gsr1 + grr1);
                        accM0[j] += gam0 * cnt; accM1[j] += gam1 * cnt;
                        aN0[t] += (gsr0 + grr0) * cnt; aN1[t] += (gsr1 + grr1) * cnt;
                        aS0[t] += gss0 * cnt;          aS1[t] += gss1 * cnt;
                        accGsr0 += m * gsr0;           accGsr1 += m * gsr1;
                        accQz += m * (gam0 * __logf(gam0 + MINI_F)
                                    + gam1 * __logf(gam1 + MINI_F));
                    } else {
                        float grr0 = tl0.x * crr0[t];
                        float grr1 = tl1.x * crr1[t];
                        const float rpm = warp_sum(grr0 + grr1) + MINI_F;
                        const float inv = __fdividef(1.0f, rpm);
                        const float lrp = __logf(rpm);
                        const float g0 = grr0 * inv, g1 = grr1 * inv;
                        const float p0 = g0 * cnt, p1 = g1 * cnt;
                        aN0[t] += p0; aN1[t] += p1;
                        accM0[j] += p0; accM1[j] += p1;
                        const float e = g0 * ((tl0.y + lc0[t]) - lrp)
                                      + g1 * ((tl1.y + lc1[t]) - lrp);
                        accQz = fmaf(m, e, accQz);
                    }
                }
            }
        }

        // write per-warp partials, cross-warp reduce, store temp_exp_n / temp_exp_s
        #pragma unroll
        for (int t = 0; t < TQ; t++) {
            sh_pN[warp][t * KD + k0] = aN0[t];
            sh_pN[warp][t * KD + k1] = aN1[t];
            sh_pS[warp][t * KD + k0] = aS0[t];
            sh_pS[warp][t * KD + k1] = aS1[t];
        }
        __syncthreads();
        {
            const int tid = threadIdx.x;   // tid = t*64 + k
            float sN = 0.0f;
            #pragma unroll
            for (int w = 0; w < 8; w++) sN += sh_pN[w][tid];
            out[OFF_N + v0 * KD + tid] = sN;
            float sS = 0.0f;
            if (tileseed) {
                #pragma unroll
                for (int w = 0; w < 8; w++) sS += sh_pS[w][tid];
            }
            out[OFF_S + v0 * KD + tid] = sS;
        }
        __syncthreads();
    }

    // epilogue: exp_m register partials -> 32-slice scratch via spread atomics
    {
        float* dst = g_scratch32 + (blockIdx.x & (NSLICE - 1)) * (BD * KD);
        #pragma unroll
        for (int j = 0; j < 8; j++) {
            atomicAdd(&dst[(b0 + j) * KD + k0], accM0[j]);
            atomicAdd(&dst[(b0 + j) * KD + k1], accM1[j]);
        }
    }
    atomicAdd(&sh_gsr[k0], accGsr0);
    atomicAdd(&sh_gsr[k1], accGsr1);
    const float qzw = warp_sum(accQz);
    if (lane == 0) atomicAdd(&sh_qz, qzw);
    __syncthreads();
    if (threadIdx.x < KD) atomicAdd(&out[OFF_GSR + threadIdx.x], sh_gsr[threadIdx.x]);
    if (threadIdx.x == 0) atomicAdd(&out[OFF_QZ], sh_qz);
}

// Sum scratch32[32][4096] -> out[0..4095]. grid (16,4): 8 slices per y-chunk.
__global__ void reduce_m_kernel(float* __restrict__ out) {
    const int i = blockIdx.x * blockDim.x + threadIdx.x;   // 0..4095
    const int j0 = blockIdx.y * 8;
    float s = 0.0f;
    #pragma unroll
    for (int j = 0; j < 8; j++)
        s += g_scratch32[(j0 + j) * (BD * KD) + i];
    atomicAdd(&out[i], s);
}

extern "C" void kernel_launch(void* const* d_in, const int* in_sizes, int n_in,
                              void* d_out, int out_size) {
    const float* BOW   = (const float*)d_in[0];
    const float* seeds = (const float*)d_in[1];
    const float* exp_m = (const float*)d_in[2];
    const float* exp_s = (const float*)d_in[3];
    const float* exp_n = (const float*)d_in[4];
    const float* pi    = (const float*)d_in[5];
    float* out = (float*)d_out;

    zero_kernel<<<128, 256>>>(out);
    colsum_kernel<<<148, 256>>>(seeds, exp_s, exp_n);
    main_kernel<<<NBLK, 256>>>(BOW, seeds, exp_m, exp_s, exp_n, pi, out);
    reduce_m_kernel<<<dim3(16, 4), 256>>>(out);
}